// round 1
// baseline (speedup 1.0000x reference)
#include <cuda_runtime.h>
#include <math.h>

#define BB 8
#define TT 2048
#define DD 1024
#define HH 64
#define NROWS (BB*TT)

#define QT 64
#define KT 64
#define PAD 65
#define FLASH_SMEM (4*QT*PAD*4)

// Scratch for projected Q/K/V (allocation-free per harness rules)
__device__ float g_q[NROWS*HH];
__device__ float g_k[NROWS*HH];
__device__ float g_v[NROWS*HH];

// ---------------------------------------------------------------------------
// QKV projection: C[16384,192] = X[16384,1024] * [Wq|Wk|Wv] + [bq|bk|bv]
// Block tile 64 rows x 192 cols, 256 threads, 4x12 register tile, K-chunk 16.
// ---------------------------------------------------------------------------
__global__ __launch_bounds__(256) void qkv_proj(
    const float* __restrict__ x,
    const float* __restrict__ Wq, const float* __restrict__ bq,
    const float* __restrict__ Wk, const float* __restrict__ bk,
    const float* __restrict__ Wv, const float* __restrict__ bv)
{
    __shared__ float Xs[64][17];
    __shared__ float Ws[16][192];
    const int tid = threadIdx.x;
    const int rid = tid >> 4;    // 0..15 -> 4 rows each
    const int cid = tid & 15;    // 0..15 -> 12 cols each (strided by 16)
    const int rowbase = blockIdx.x * 64;

    float acc[4][12];
    #pragma unroll
    for (int i = 0; i < 4; i++)
        #pragma unroll
        for (int j = 0; j < 12; j++) acc[i][j] = 0.f;

    for (int k0 = 0; k0 < DD; k0 += 16) {
        // Load X tile 64x16
        #pragma unroll
        for (int p = 0; p < 4; p++) {
            int idx = tid + p * 256;          // < 1024
            int r = idx >> 4, kk = idx & 15;
            Xs[r][kk] = x[(size_t)(rowbase + r) * DD + k0 + kk];
        }
        // Load W tile 16x192 (Wq | Wk | Wv)
        #pragma unroll
        for (int p = 0; p < 12; p++) {
            int idx = tid + p * 256;          // < 3072
            int kk = idx / 192, c = idx % 192;
            const float* W = (c < 64) ? Wq : (c < 128 ? Wk : Wv);
            Ws[kk][c] = W[(k0 + kk) * HH + (c & 63)];
        }
        __syncthreads();

        #pragma unroll
        for (int kk = 0; kk < 16; kk++) {
            float xa[4], wv[12];
            #pragma unroll
            for (int i = 0; i < 4; i++) xa[i] = Xs[rid * 4 + i][kk];
            #pragma unroll
            for (int j = 0; j < 12; j++) wv[j] = Ws[kk][cid + 16 * j];
            #pragma unroll
            for (int i = 0; i < 4; i++)
                #pragma unroll
                for (int j = 0; j < 12; j++)
                    acc[i][j] += xa[i] * wv[j];
        }
        __syncthreads();
    }

    // Epilogue: bias + scatter to g_q / g_k / g_v
    #pragma unroll
    for (int i = 0; i < 4; i++) {
        int row = rowbase + rid * 4 + i;
        #pragma unroll
        for (int j = 0; j < 12; j++) {
            int c = cid + 16 * j;
            float val = acc[i][j];
            if (c < 64)       g_q[(size_t)row * HH + c]         = val + bq[c];
            else if (c < 128) g_k[(size_t)row * HH + (c - 64)]  = val + bk[c - 64];
            else              g_v[(size_t)row * HH + (c - 128)] = val + bv[c - 128];
        }
    }
}

// ---------------------------------------------------------------------------
// Flash attention (causal), fp32. One CTA per (batch, 64-row q tile).
// 256 threads as 16x16: ty -> 4 q-rows, tx -> 4 k-cols / 4 o-dims.
// ---------------------------------------------------------------------------
__global__ __launch_bounds__(256) void flash(float* __restrict__ out)
{
    extern __shared__ float sm[];
    float (*Qs)[PAD] = (float(*)[PAD])(sm);
    float (*Ks)[PAD] = (float(*)[PAD])(sm + QT * PAD);
    float (*Vs)[PAD] = (float(*)[PAD])(sm + 2 * QT * PAD);
    float (*Ps)[PAD] = (float(*)[PAD])(sm + 3 * QT * PAD);

    const int tid = threadIdx.x;
    const int ty = tid >> 4;     // q-row group
    const int tx = tid & 15;     // k-col / dim group
    const int qtile = blockIdx.x;
    const int b = blockIdx.y;
    const int qbase = qtile * QT;
    const size_t head_off = (size_t)b * TT * HH;

    // Load Q tile (64x64) via float4
    {
        const float4* Q4 = (const float4*)(g_q + head_off + (size_t)qbase * HH);
        #pragma unroll
        for (int p = 0; p < 4; p++) {
            int idx = tid + p * 256;     // < 1024 float4s
            int r = idx >> 4, d4 = idx & 15;
            float4 v = Q4[idx];
            Qs[r][d4 * 4 + 0] = v.x; Qs[r][d4 * 4 + 1] = v.y;
            Qs[r][d4 * 4 + 2] = v.z; Qs[r][d4 * 4 + 3] = v.w;
        }
    }

    float O[4][4];
    float m[4], l[4];
    #pragma unroll
    for (int i = 0; i < 4; i++) {
        m[i] = -1e30f; l[i] = 0.f;
        #pragma unroll
        for (int j = 0; j < 4; j++) O[i][j] = 0.f;
    }
    const float scale = 0.125f;  // 1/sqrt(64)

    for (int kt = 0; kt <= qtile; kt++) {
        const int kbase = kt * KT;
        __syncthreads();  // previous iteration's readers of Ks/Vs/Ps done; Q load done
        const float4* K4 = (const float4*)(g_k + head_off + (size_t)kbase * HH);
        const float4* V4 = (const float4*)(g_v + head_off + (size_t)kbase * HH);
        #pragma unroll
        for (int p = 0; p < 4; p++) {
            int idx = tid + p * 256;
            int r = idx >> 4, d4 = idx & 15;
            float4 kv = K4[idx];
            Ks[r][d4 * 4 + 0] = kv.x; Ks[r][d4 * 4 + 1] = kv.y;
            Ks[r][d4 * 4 + 2] = kv.z; Ks[r][d4 * 4 + 3] = kv.w;
            float4 vv = V4[idx];
            Vs[r][d4 * 4 + 0] = vv.x; Vs[r][d4 * 4 + 1] = vv.y;
            Vs[r][d4 * 4 + 2] = vv.z; Vs[r][d4 * 4 + 3] = vv.w;
        }
        __syncthreads();

        // S = Q K^T (4x4 per thread)
        float S[4][4];
        #pragma unroll
        for (int i = 0; i < 4; i++)
            #pragma unroll
            for (int j = 0; j < 4; j++) S[i][j] = 0.f;
        #pragma unroll 8
        for (int d = 0; d < 64; d++) {
            float qa[4], kb[4];
            #pragma unroll
            for (int i = 0; i < 4; i++) qa[i] = Qs[ty * 4 + i][d];
            #pragma unroll
            for (int j = 0; j < 4; j++) kb[j] = Ks[tx * 4 + j][d];
            #pragma unroll
            for (int i = 0; i < 4; i++)
                #pragma unroll
                for (int j = 0; j < 4; j++)
                    S[i][j] += qa[i] * kb[j];
        }

        const bool diag = (kt == qtile);
        float mnew[4];
        #pragma unroll
        for (int i = 0; i < 4; i++) {
            int qg = qbase + ty * 4 + i;
            float rmax = -1e30f;
            #pragma unroll
            for (int j = 0; j < 4; j++) {
                int kg = kbase + tx * 4 + j;
                float s = S[i][j] * scale;
                if (diag && kg > qg) s = -1e30f;
                S[i][j] = s;
                rmax = fmaxf(rmax, s);
            }
            #pragma unroll
            for (int off = 8; off; off >>= 1)
                rmax = fmaxf(rmax, __shfl_xor_sync(0xffffffffu, rmax, off, 16));
            mnew[i] = fmaxf(m[i], rmax);
        }
        #pragma unroll
        for (int i = 0; i < 4; i++) {
            float rsum = 0.f;
            #pragma unroll
            for (int j = 0; j < 4; j++) {
                float p = __expf(S[i][j] - mnew[i]);
                S[i][j] = p;
                rsum += p;
            }
            #pragma unroll
            for (int off = 8; off; off >>= 1)
                rsum += __shfl_xor_sync(0xffffffffu, rsum, off, 16);
            float alpha = __expf(m[i] - mnew[i]);
            l[i] = l[i] * alpha + rsum;
            m[i] = mnew[i];
            #pragma unroll
            for (int j = 0; j < 4; j++) O[i][j] *= alpha;
        }
        // Stage P through smem
        #pragma unroll
        for (int i = 0; i < 4; i++)
            #pragma unroll
            for (int j = 0; j < 4; j++)
                Ps[ty * 4 + i][tx * 4 + j] = S[i][j];
        __syncthreads();

        // O += P * V
        #pragma unroll 8
        for (int k = 0; k < 64; k++) {
            float pa[4], vb[4];
            #pragma unroll
            for (int i = 0; i < 4; i++) pa[i] = Ps[ty * 4 + i][k];
            #pragma unroll
            for (int j = 0; j < 4; j++) vb[j] = Vs[k][tx * 4 + j];
            #pragma unroll
            for (int i = 0; i < 4; i++)
                #pragma unroll
                for (int j = 0; j < 4; j++)
                    O[i][j] += pa[i] * vb[j];
        }
    }

    // Normalize + write out [B,T,H] fp32
    #pragma unroll
    for (int i = 0; i < 4; i++) {
        float inv = 1.f / l[i];
        int r = qbase + ty * 4 + i;
        #pragma unroll
        for (int j = 0; j < 4; j++)
            out[head_off + (size_t)r * HH + tx * 4 + j] = O[i][j] * inv;
    }
}

extern "C" void kernel_launch(void* const* d_in, const int* in_sizes, int n_in,
                              void* d_out, int out_size)
{
    const float* x  = (const float*)d_in[0];
    const float* Wq = (const float*)d_in[1];
    const float* bq = (const float*)d_in[2];
    const float* Wk = (const float*)d_in[3];
    const float* bk = (const float*)d_in[4];
    const float* Wv = (const float*)d_in[5];
    const float* bv = (const float*)d_in[6];
    float* out = (float*)d_out;

    qkv_proj<<<NROWS / 64, 256>>>(x, Wq, bq, Wk, bk, Wv, bv);

    // Host-side attribute set (not a stream op; idempotent, deterministic)
    cudaFuncSetAttribute(flash, cudaFuncAttributeMaxDynamicSharedMemorySize, FLASH_SMEM);
    dim3 g(TT / QT, BB);
    flash<<<g, 256, FLASH_SMEM>>>(out);
}

// round 2
// speedup vs baseline: 1.4736x; 1.4736x over previous
#include <cuda_runtime.h>
#include <math.h>

#define BB 8
#define TT 2048
#define DD 1024
#define HH 64
#define NROWS (BB*TT)

#define QT 64
#define KT 64
#define FLASH_SMEM (4*64*64*4)   // Qt,Kt,Vs,Pt each 64x64 fp32 = 64KB

// Scratch for projected Q/K/V
__device__ float g_q[NROWS*HH];
__device__ float g_k[NROWS*HH];
__device__ float g_v[NROWS*HH];

// ---------------------------------------------------------------------------
// QKV projection: C[16384,192] = X[16384,1024] * [Wq|Wk|Wv] + bias
// 64x192 tile per CTA, 256 threads, 4 rows x 12 contiguous cols per thread.
// ---------------------------------------------------------------------------
__global__ __launch_bounds__(256) void qkv_proj(
    const float* __restrict__ x,
    const float* __restrict__ Wq, const float* __restrict__ bq,
    const float* __restrict__ Wk, const float* __restrict__ bk,
    const float* __restrict__ Wv, const float* __restrict__ bv)
{
    __shared__ float Xt[16*64];     // [kk][row], word-swizzled
    __shared__ float Ws[16*192];    // [kk][col], row-major
    const int tid = threadIdx.x;
    const int rid = tid >> 4;       // 0..15 -> rows rid*4..rid*4+3
    const int cid = tid & 15;       // 0..15 -> cols cid*12..cid*12+11
    const int rowbase = blockIdx.x * 64;

    float acc[4][12];
    #pragma unroll
    for (int i = 0; i < 4; i++)
        #pragma unroll
        for (int j = 0; j < 12; j++) acc[i][j] = 0.f;

    const int xrow = tid >> 2;      // 0..63
    const int xkc  = tid & 3;       // 0..3 (float4 chunk of k)

    for (int k0 = 0; k0 < DD; k0 += 16) {
        // X tile 64x16 -> transposed swizzled Xt[kk][row]
        {
            float4 xv = *(const float4*)(x + (size_t)(rowbase + xrow) * DD + k0 + xkc * 4);
            float c[4] = {xv.x, xv.y, xv.z, xv.w};
            #pragma unroll
            for (int q = 0; q < 4; q++) {
                int kk = xkc * 4 + q;
                Xt[kk * 64 + (((xrow >> 2) ^ kk) << 2) + (xrow & 3)] = c[q];
            }
        }
        // W tile 16x192 (Wq|Wk|Wv), float4 loads
        #pragma unroll
        for (int p = 0; p < 3; p++) {
            int idx = tid + p * 256;        // < 768
            int kk = idx / 48, c4 = idx % 48;
            float4 wv;
            if (c4 < 16)       wv = *(const float4*)(Wq + (size_t)(k0 + kk) * HH + c4 * 4);
            else if (c4 < 32)  wv = *(const float4*)(Wk + (size_t)(k0 + kk) * HH + (c4 - 16) * 4);
            else               wv = *(const float4*)(Wv + (size_t)(k0 + kk) * HH + (c4 - 32) * 4);
            *(float4*)(Ws + kk * 192 + c4 * 4) = wv;
        }
        __syncthreads();

        #pragma unroll
        for (int kk = 0; kk < 16; kk++) {
            float xa[4];
            *(float4*)xa = *(const float4*)(Xt + kk * 64 + ((rid ^ kk) << 2));
            float wr[12];
            *(float4*)(wr + 0) = *(const float4*)(Ws + kk * 192 + cid * 12 + 0);
            *(float4*)(wr + 4) = *(const float4*)(Ws + kk * 192 + cid * 12 + 4);
            *(float4*)(wr + 8) = *(const float4*)(Ws + kk * 192 + cid * 12 + 8);
            #pragma unroll
            for (int i = 0; i < 4; i++)
                #pragma unroll
                for (int j = 0; j < 12; j++)
                    acc[i][j] += xa[i] * wr[j];
        }
        __syncthreads();
    }

    // Epilogue: bias + scatter
    #pragma unroll
    for (int i = 0; i < 4; i++) {
        int row = rowbase + rid * 4 + i;
        #pragma unroll
        for (int j = 0; j < 12; j++) {
            int c = cid * 12 + j;
            float val = acc[i][j];
            if (c < 64)       g_q[(size_t)row * HH + c]         = val + bq[c];
            else if (c < 128) g_k[(size_t)row * HH + (c - 64)]  = val + bk[c - 64];
            else              g_v[(size_t)row * HH + (c - 128)] = val + bv[c - 128];
        }
    }
}

// ---------------------------------------------------------------------------
// Flash attention (causal), fp32, balanced pairing: CTA (p,b) handles
// q-tiles p and 31-p of batch b => exactly 33 k-tile units per CTA.
// 256 threads as 16x16: ty -> 4 q-rows, tx -> 4 k-cols / 4 out-dims.
// Smem layouts transposed + word-swizzled for LDS.128 conflict-free reads.
// ---------------------------------------------------------------------------
__global__ __launch_bounds__(256) void flash(float* __restrict__ out)
{
    extern __shared__ float sm[];
    float* Qt = sm;              // [d][row]  swizzled
    float* Kt = sm + 4096;       // [d][col]  swizzled
    float* Vs = sm + 8192;       // [k][col]  row-major
    float* Pt = sm + 12288;      // [k][row]  swizzled

    const int tid = threadIdx.x;
    const int ty = tid >> 4;     // 0..15
    const int tx = tid & 15;     // 0..15
    const int pr = blockIdx.x;   // pair index 0..15
    const int b  = blockIdx.y;
    const size_t head_off = (size_t)b * TT * HH;
    const float scale = 0.125f * 1.44269504f;   // 1/sqrt(64) * log2(e)

    #pragma unroll 1
    for (int half = 0; half < 2; half++) {
        const int qtile = half ? (31 - pr) : pr;
        const int qbase = qtile * QT;

        __syncthreads();   // smem reuse across halves
        // Load Q tile -> transposed swizzled Qt[d][row]
        {
            const float4* Q4 = (const float4*)(g_q + head_off + (size_t)qbase * HH);
            #pragma unroll
            for (int p = 0; p < 4; p++) {
                int idx = tid + p * 256;
                int r = idx >> 4, d4 = idx & 15;
                float4 v = Q4[idx];
                int off = (((r >> 2) ^ d4) << 2) + (r & 3);
                Qt[(4 * d4 + 0) * 64 + off] = v.x;
                Qt[(4 * d4 + 1) * 64 + off] = v.y;
                Qt[(4 * d4 + 2) * 64 + off] = v.z;
                Qt[(4 * d4 + 3) * 64 + off] = v.w;
            }
        }

        float O[4][4];
        float m[4], l[4];
        #pragma unroll
        for (int i = 0; i < 4; i++) {
            m[i] = -1e30f; l[i] = 0.f;
            #pragma unroll
            for (int j = 0; j < 4; j++) O[i][j] = 0.f;
        }

        for (int kt = 0; kt <= qtile; kt++) {
            const int kbase = kt * KT;
            __syncthreads();   // prior readers of Kt/Vs/Pt done; Q store done
            {
                const float4* K4 = (const float4*)(g_k + head_off + (size_t)kbase * HH);
                const float4* V4 = (const float4*)(g_v + head_off + (size_t)kbase * HH);
                #pragma unroll
                for (int p = 0; p < 4; p++) {
                    int idx = tid + p * 256;
                    int r = idx >> 4, d4 = idx & 15;
                    float4 kv = K4[idx];
                    int off = (((r >> 2) ^ d4) << 2) + (r & 3);
                    Kt[(4 * d4 + 0) * 64 + off] = kv.x;
                    Kt[(4 * d4 + 1) * 64 + off] = kv.y;
                    Kt[(4 * d4 + 2) * 64 + off] = kv.z;
                    Kt[(4 * d4 + 3) * 64 + off] = kv.w;
                    float4 vv = V4[idx];
                    *(float4*)(Vs + r * 64 + d4 * 4) = vv;
                }
            }
            __syncthreads();

            // S = Q K^T, 4x4 per thread
            float S[4][4];
            #pragma unroll
            for (int i = 0; i < 4; i++)
                #pragma unroll
                for (int j = 0; j < 4; j++) S[i][j] = 0.f;
            #pragma unroll 8
            for (int d = 0; d < 64; d++) {
                int sw = d >> 2;
                float qa[4], kb[4];
                *(float4*)qa = *(const float4*)(Qt + d * 64 + ((ty ^ sw) << 2));
                *(float4*)kb = *(const float4*)(Kt + d * 64 + ((tx ^ sw) << 2));
                #pragma unroll
                for (int i = 0; i < 4; i++)
                    #pragma unroll
                    for (int j = 0; j < 4; j++)
                        S[i][j] += qa[i] * kb[j];
            }

            const bool diag = (kt == qtile);
            float mnew[4];
            #pragma unroll
            for (int i = 0; i < 4; i++) {
                int qg = qbase + ty * 4 + i;
                float rmax = -1e30f;
                #pragma unroll
                for (int j = 0; j < 4; j++) {
                    int kg = kbase + tx * 4 + j;
                    float s = S[i][j] * scale;
                    if (diag && kg > qg) s = -1e30f;
                    S[i][j] = s;
                    rmax = fmaxf(rmax, s);
                }
                #pragma unroll
                for (int off = 8; off; off >>= 1)
                    rmax = fmaxf(rmax, __shfl_xor_sync(0xffffffffu, rmax, off, 16));
                mnew[i] = fmaxf(m[i], rmax);
            }
            #pragma unroll
            for (int i = 0; i < 4; i++) {
                float rsum = 0.f;
                #pragma unroll
                for (int j = 0; j < 4; j++) {
                    float p = exp2f(S[i][j] - mnew[i]);
                    S[i][j] = p;
                    rsum += p;
                }
                #pragma unroll
                for (int off = 8; off; off >>= 1)
                    rsum += __shfl_xor_sync(0xffffffffu, rsum, off, 16);
                float alpha = exp2f(m[i] - mnew[i]);
                l[i] = l[i] * alpha + rsum;
                m[i] = mnew[i];
                #pragma unroll
                for (int j = 0; j < 4; j++) O[i][j] *= alpha;
            }

            // Stage P transposed+swizzled: Pt[k=tx*4+j][row ty*4..+3]
            #pragma unroll
            for (int j = 0; j < 4; j++) {
                float4 pv = make_float4(S[0][j], S[1][j], S[2][j], S[3][j]);
                *(float4*)(Pt + (tx * 4 + j) * 64 + ((ty ^ tx) << 2)) = pv;
            }
            __syncthreads();

            // O += P * V
            #pragma unroll 8
            for (int k = 0; k < 64; k++) {
                int sw = k >> 2;
                float pa[4], vb[4];
                *(float4*)pa = *(const float4*)(Pt + k * 64 + ((ty ^ sw) << 2));
                *(float4*)vb = *(const float4*)(Vs + k * 64 + tx * 4);
                #pragma unroll
                for (int i = 0; i < 4; i++)
                    #pragma unroll
                    for (int j = 0; j < 4; j++)
                        O[i][j] += pa[i] * vb[j];
            }
        }

        // Normalize + write out [B,T,H]
        #pragma unroll
        for (int i = 0; i < 4; i++) {
            float inv = 1.f / l[i];
            int r = qbase + ty * 4 + i;
            float4 ov = make_float4(O[i][0] * inv, O[i][1] * inv, O[i][2] * inv, O[i][3] * inv);
            *(float4*)(out + head_off + (size_t)r * HH + tx * 4) = ov;
        }
    }
}

extern "C" void kernel_launch(void* const* d_in, const int* in_sizes, int n_in,
                              void* d_out, int out_size)
{
    const float* x  = (const float*)d_in[0];
    const float* Wq = (const float*)d_in[1];
    const float* bq = (const float*)d_in[2];
    const float* Wk = (const float*)d_in[3];
    const float* bk = (const float*)d_in[4];
    const float* Wv = (const float*)d_in[5];
    const float* bv = (const float*)d_in[6];
    float* out = (float*)d_out;

    qkv_proj<<<NROWS / 64, 256>>>(x, Wq, bq, Wk, bk, Wv, bv);

    cudaFuncSetAttribute(flash, cudaFuncAttributeMaxDynamicSharedMemorySize, FLASH_SMEM);
    dim3 g(16, BB);   // 16 balanced pairs x 8 batches = 128 CTAs
    flash<<<g, 256, FLASH_SMEM>>>(out);
}

// round 4
// speedup vs baseline: 3.9307x; 2.6675x over previous
#include <cuda_runtime.h>
#include <cuda_bf16.h>
#include <math.h>
#include <stdint.h>

#define BB 8
#define TT 2048
#define DD 1024
#define HH 64
#define NROWS (BB*TT)

// ---------------------------------------------------------------------------
// bf16 hi/lo split Q/K/V scratch (written by proj, read by flash)
// ---------------------------------------------------------------------------
__device__ __nv_bfloat16 g_qh[NROWS*HH], g_ql[NROWS*HH];
__device__ __nv_bfloat16 g_kh[NROWS*HH], g_kl[NROWS*HH];
__device__ __nv_bfloat16 g_vh[NROWS*HH], g_vl[NROWS*HH];
__device__ __nv_bfloat16 g_wt_h[192*DD];   // W^T hi  [n][k]  (q part pre-scaled)
__device__ __nv_bfloat16 g_wt_l[192*DD];   // W^T lo  [n][k]

#define QSCALE (0.125f * 1.44269504f)      // 1/sqrt(64) * log2(e), folded into Wq/bq

// ---------------------------------------------------------------------------
// Helpers (base sm_100 ISA only: ldmatrix / mma.sync / cp.async)
// ---------------------------------------------------------------------------
__device__ __forceinline__ uint32_t smem_u32(const void* p) {
    uint32_t a;
    asm("{ .reg .u64 t; cvta.to.shared.u64 t, %1; cvt.u32.u64 %0, t; }" : "=r"(a) : "l"(p));
    return a;
}
__device__ __forceinline__ void ldm_x4(uint32_t* r, uint32_t addr) {
    asm volatile("ldmatrix.sync.aligned.m8n8.x4.shared.b16 {%0,%1,%2,%3}, [%4];"
                 : "=r"(r[0]), "=r"(r[1]), "=r"(r[2]), "=r"(r[3]) : "r"(addr));
}
__device__ __forceinline__ void ldm_x4_t(uint32_t* r, uint32_t addr) {
    asm volatile("ldmatrix.sync.aligned.m8n8.x4.trans.shared.b16 {%0,%1,%2,%3}, [%4];"
                 : "=r"(r[0]), "=r"(r[1]), "=r"(r[2]), "=r"(r[3]) : "r"(addr));
}
__device__ __forceinline__ void mma_bf16(float* c, const uint32_t* a, uint32_t b0, uint32_t b1) {
    asm volatile("mma.sync.aligned.m16n8k16.row.col.f32.bf16.bf16.f32 "
        "{%0,%1,%2,%3}, {%4,%5,%6,%7}, {%8,%9}, {%0,%1,%2,%3};"
        : "+f"(c[0]), "+f"(c[1]), "+f"(c[2]), "+f"(c[3])
        : "r"(a[0]), "r"(a[1]), "r"(a[2]), "r"(a[3]), "r"(b0), "r"(b1));
}
__device__ __forceinline__ uint32_t pack_bf16(float lo, float hi) {
    uint32_t d;
    asm("cvt.rn.bf16x2.f32 %0, %1, %2;" : "=r"(d) : "f"(hi), "f"(lo));
    return d;
}
__device__ __forceinline__ float blo(uint32_t u) { return __uint_as_float(u << 16); }
__device__ __forceinline__ float bhi(uint32_t u) { return __uint_as_float(u & 0xFFFF0000u); }

__device__ __forceinline__ void cp16(uint32_t dst, const void* src) {
    asm volatile("cp.async.cg.shared.global [%0], [%1], 16;"
                 :: "r"(dst), "l"(__cvta_generic_to_global(src)));
}
#define CP_COMMIT() asm volatile("cp.async.commit_group;" ::: "memory")
#define CP_WAIT0()  asm volatile("cp.async.wait_group 0;" ::: "memory")
#define CP_WAIT1()  asm volatile("cp.async.wait_group 1;" ::: "memory")

// ---------------------------------------------------------------------------
// W transpose + bf16 hi/lo split (q part scaled by QSCALE)
// ---------------------------------------------------------------------------
__global__ __launch_bounds__(256) void wprep(const float* __restrict__ Wq,
                                             const float* __restrict__ Wk,
                                             const float* __restrict__ Wv)
{
    int idx = blockIdx.x * 256 + threadIdx.x;     // < 192*1024
    int n = idx >> 10, k = idx & 1023;
    const float* W = (n < 64) ? Wq : (n < 128 ? Wk : Wv);
    float v = W[(size_t)k * HH + (n & 63)];
    if (n < 64) v *= QSCALE;
    __nv_bfloat16 h = __float2bfloat16_rn(v);
    g_wt_h[idx] = h;
    g_wt_l[idx] = __float2bfloat16_rn(v - __bfloat162float(h));
}

// ---------------------------------------------------------------------------
// QKV projection via mma.sync bf16-split. CTA: M=128 x N=192, K chunks of 64.
// 8 warps: warpM (0-3) x warpN (0-1); warp tile 32 x 96.
// ---------------------------------------------------------------------------
#define PJ_AH 0
#define PJ_AL 16384
#define PJ_BH 32768
#define PJ_BL 57344
#define PROJ_SMEM 81920

__global__ __launch_bounds__(256) void proj_mma(
    const float* __restrict__ x,
    const float* __restrict__ bq, const float* __restrict__ bk, const float* __restrict__ bv)
{
    extern __shared__ __align__(1024) char smem[];
    const uint32_t sb = smem_u32(smem);
    const int tid = threadIdx.x;
    const int wid = tid >> 5, lane = tid & 31;
    const int warpM = wid >> 1, warpN = wid & 1;
    const int rowbase = blockIdx.x * 128;

    float acc[2][12][4];
    #pragma unroll
    for (int m = 0; m < 2; m++)
        #pragma unroll
        for (int n = 0; n < 12; n++)
            #pragma unroll
            for (int e = 0; e < 4; e++) acc[m][n][e] = 0.f;

    const int l15 = lane & 15, lh = lane >> 4;

    for (int c = 0; c < 16; c++) {
        const int k0 = c * 64;
        __syncthreads();
        // A tile: x fp32 -> bf16 hi/lo, SW128 swizzled, rows of 128B
        #pragma unroll
        for (int p = 0; p < 8; p++) {
            int idx = tid + p * 256;            // < 2048
            int r = idx >> 4, c4 = idx & 15;
            float4 v = *(const float4*)(x + (size_t)(rowbase + r) * DD + k0 + c4 * 4);
            uint32_t h01 = pack_bf16(v.x, v.y), h23 = pack_bf16(v.z, v.w);
            uint32_t l01 = pack_bf16(v.x - blo(h01), v.y - bhi(h01));
            uint32_t l23 = pack_bf16(v.z - blo(h23), v.w - bhi(h23));
            int sw = r * 128 + ((((c4 >> 1) ^ (r & 7)) << 4)) + (c4 & 1) * 8;
            *(uint2*)(smem + PJ_AH + sw) = make_uint2(h01, h23);
            *(uint2*)(smem + PJ_AL + sw) = make_uint2(l01, l23);
        }
        // B tile: Wt[0..191][k0..+63] bf16 hi/lo, swizzled
        #pragma unroll
        for (int p = 0; p < 6; p++) {
            int idx = tid + p * 256;            // < 1536
            int r = idx >> 3, c8 = idx & 7;
            uint4 hv = *(const uint4*)(g_wt_h + (size_t)r * DD + k0 + c8 * 8);
            uint4 lv = *(const uint4*)(g_wt_l + (size_t)r * DD + k0 + c8 * 8);
            int sw = r * 128 + ((c8 ^ (r & 7)) << 4);
            *(uint4*)(smem + PJ_BH + sw) = hv;
            *(uint4*)(smem + PJ_BL + sw) = lv;
        }
        __syncthreads();

        #pragma unroll
        for (int ks = 0; ks < 4; ks++) {
            uint32_t ah[2][4], al[2][4];
            #pragma unroll
            for (int m = 0; m < 2; m++) {
                int row = warpM * 32 + m * 16 + l15;
                uint32_t a = sb + row * 128 + ((((ks * 2 + lh) ^ (row & 7)) << 4));
                ldm_x4(ah[m], a + PJ_AH);
                ldm_x4(al[m], a + PJ_AL);
            }
            #pragma unroll
            for (int np = 0; np < 6; np++) {
                int n = warpN * 96 + np * 16 + l15;
                uint32_t a = sb + n * 128 + ((((ks * 2 + lh) ^ (n & 7)) << 4));
                uint32_t bh[4], bl[4];
                ldm_x4(bh, a + PJ_BH);
                ldm_x4(bl, a + PJ_BL);
                #pragma unroll
                for (int m = 0; m < 2; m++)
                    #pragma unroll
                    for (int sub = 0; sub < 2; sub++) {
                        float* cc = acc[m][np * 2 + sub];
                        mma_bf16(cc, ah[m], bh[sub], bh[sub + 2]);
                        mma_bf16(cc, ah[m], bl[sub], bl[sub + 2]);
                        mma_bf16(cc, al[m], bh[sub], bh[sub + 2]);
                    }
            }
        }
    }

    // Epilogue: bias + bf16 hi/lo split store
    #pragma unroll
    for (int m = 0; m < 2; m++) {
        int r0 = rowbase + warpM * 32 + m * 16 + (lane >> 2);
        #pragma unroll
        for (int nt = 0; nt < 12; nt++) {
            int g = warpN * 96 + nt * 8 + (lane & 3) * 2;
            __nv_bfloat16 *dh, *dl; const float* bias; int cc; float s;
            if (g < 64)       { dh = g_qh; dl = g_ql; bias = bq; cc = g;       s = QSCALE; }
            else if (g < 128) { dh = g_kh; dl = g_kl; bias = bk; cc = g - 64;  s = 1.f; }
            else              { dh = g_vh; dl = g_vl; bias = bv; cc = g - 128; s = 1.f; }
            float b0 = bias[cc] * s, b1 = bias[cc + 1] * s;
            float v0 = acc[m][nt][0] + b0, v1 = acc[m][nt][1] + b1;
            float v2 = acc[m][nt][2] + b0, v3 = acc[m][nt][3] + b1;
            uint32_t h0 = pack_bf16(v0, v1);
            uint32_t l0 = pack_bf16(v0 - blo(h0), v1 - bhi(h0));
            uint32_t h1 = pack_bf16(v2, v3);
            uint32_t l1 = pack_bf16(v2 - blo(h1), v3 - bhi(h1));
            *(uint32_t*)((char*)dh + ((size_t)r0 * 64 + cc) * 2) = h0;
            *(uint32_t*)((char*)dl + ((size_t)r0 * 64 + cc) * 2) = l0;
            *(uint32_t*)((char*)dh + ((size_t)(r0 + 8) * 64 + cc) * 2) = h1;
            *(uint32_t*)((char*)dl + ((size_t)(r0 + 8) * 64 + cc) * 2) = l1;
        }
    }
}

// ---------------------------------------------------------------------------
// Flash attention (causal) via mma.sync bf16-split.
// CTA = 128 threads, 4 warps, each warp one 16-row m-tile of a 64-row q tile.
// Balanced pairing: CTA pr handles q-tiles pr and 31-pr (33 kt units).
// cp.async double-buffered K/V tiles.
// ---------------------------------------------------------------------------
#define FL_QH 0
#define FL_QL 8192
#define FL_BUF 16384        // 2 x { KH, KL, VH, VL } x 8KB
#define FLASH_SMEM (16384 + 2*32768)

__global__ __launch_bounds__(128) void flash(float* __restrict__ out)
{
    extern __shared__ __align__(1024) char smem[];
    const uint32_t sb = smem_u32(smem);
    const int tid = threadIdx.x;
    const int wid = tid >> 5, lane = tid & 31;
    const int l15 = lane & 15, lh = lane >> 4;
    const int pr = blockIdx.x;
    const int b  = blockIdx.y;
    const size_t hb = (size_t)b * TT * HH;

    #pragma unroll 1
    for (int half = 0; half < 2; half++) {
        const int qtile = half ? (31 - pr) : pr;
        const int qbase = qtile * 64;

        // Issue Q + kt0 loads (group 0)
        #pragma unroll
        for (int i = 0; i < 8; i++) {
            int idx = tid + i * 128;                 // < 1024
            int arr = idx >> 9, rem = idx & 511;
            int row = rem >> 3, cc = rem & 7;
            const __nv_bfloat16* src = (arr == 0 ? g_qh : g_ql) + hb + (size_t)(qbase + row) * 64 + cc * 8;
            cp16(sb + (arr ? FL_QL : FL_QH) + row * 128 + (((cc ^ (row & 7)) << 4)), src);
        }
        #pragma unroll
        for (int i = 0; i < 16; i++) {
            int idx = tid + i * 128;                 // < 2048
            int arr = idx >> 9, rem = idx & 511;
            int row = rem >> 3, cc = rem & 7;
            const __nv_bfloat16* base = arr == 0 ? g_kh : arr == 1 ? g_kl : arr == 2 ? g_vh : g_vl;
            cp16(sb + FL_BUF + arr * 8192 + row * 128 + (((cc ^ (row & 7)) << 4)),
                 base + hb + (size_t)row * 64 + cc * 8);
        }
        CP_COMMIT();

        float O[8][4];
        float m0 = -1e30f, m1 = -1e30f, l0 = 0.f, l1 = 0.f;
        #pragma unroll
        for (int j = 0; j < 8; j++)
            #pragma unroll
            for (int e = 0; e < 4; e++) O[j][e] = 0.f;

        uint32_t Qh[4][4], Ql[4][4];

        for (int kt = 0; kt <= qtile; kt++) {
            const uint32_t bufb = sb + FL_BUF + (kt & 1) * 32768;
            if (kt < qtile) {
                const int kb2 = (kt + 1) * 64;
                const uint32_t nb = sb + FL_BUF + ((kt + 1) & 1) * 32768;
                #pragma unroll
                for (int i = 0; i < 16; i++) {
                    int idx = tid + i * 128;
                    int arr = idx >> 9, rem = idx & 511;
                    int row = rem >> 3, cc = rem & 7;
                    const __nv_bfloat16* base = arr == 0 ? g_kh : arr == 1 ? g_kl : arr == 2 ? g_vh : g_vl;
                    cp16(nb + arr * 8192 + row * 128 + (((cc ^ (row & 7)) << 4)),
                         base + hb + (size_t)(kb2 + row) * 64 + cc * 8);
                }
                CP_COMMIT();
                CP_WAIT1();
            } else {
                CP_WAIT0();
            }
            __syncthreads();

            if (kt == 0) {   // cache Q fragments
                #pragma unroll
                for (int ks = 0; ks < 4; ks++) {
                    int row = wid * 16 + l15;
                    uint32_t a = sb + row * 128 + ((((ks * 2 + lh) ^ (row & 7)) << 4));
                    ldm_x4(Qh[ks], a + FL_QH);
                    ldm_x4(Ql[ks], a + FL_QL);
                }
            }

            // ---- S = Q K^T ----
            float S[8][4];
            #pragma unroll
            for (int j = 0; j < 8; j++)
                #pragma unroll
                for (int e = 0; e < 4; e++) S[j][e] = 0.f;
            #pragma unroll
            for (int ks = 0; ks < 4; ks++)
                #pragma unroll
                for (int kp = 0; kp < 4; kp++) {
                    int n = kp * 16 + l15;
                    uint32_t a = bufb + n * 128 + ((((ks * 2 + lh) ^ (n & 7)) << 4));
                    uint32_t kh[4], kl[4];
                    ldm_x4(kh, a);            // KH at +0
                    ldm_x4(kl, a + 8192);     // KL
                    #pragma unroll
                    for (int sub = 0; sub < 2; sub++) {
                        float* cc = S[kp * 2 + sub];
                        mma_bf16(cc, Qh[ks], kh[sub], kh[sub + 2]);
                        mma_bf16(cc, Qh[ks], kl[sub], kl[sub + 2]);
                        mma_bf16(cc, Ql[ks], kh[sub], kh[sub + 2]);
                    }
                }

            // ---- causal mask on diagonal tile ----
            const int rl0 = wid * 16 + (lane >> 2), rl1 = rl0 + 8;
            if (kt == qtile) {
                #pragma unroll
                for (int j = 0; j < 8; j++) {
                    int kc = j * 8 + (lane & 3) * 2;
                    if (kc     > rl0) S[j][0] = -1e30f;
                    if (kc + 1 > rl0) S[j][1] = -1e30f;
                    if (kc     > rl1) S[j][2] = -1e30f;
                    if (kc + 1 > rl1) S[j][3] = -1e30f;
                }
            }

            // ---- online softmax (scores already in log2 units) ----
            float mx0 = -1e30f, mx1 = -1e30f;
            #pragma unroll
            for (int j = 0; j < 8; j++) {
                mx0 = fmaxf(mx0, fmaxf(S[j][0], S[j][1]));
                mx1 = fmaxf(mx1, fmaxf(S[j][2], S[j][3]));
            }
            mx0 = fmaxf(mx0, __shfl_xor_sync(0xffffffffu, mx0, 1));
            mx0 = fmaxf(mx0, __shfl_xor_sync(0xffffffffu, mx0, 2));
            mx1 = fmaxf(mx1, __shfl_xor_sync(0xffffffffu, mx1, 1));
            mx1 = fmaxf(mx1, __shfl_xor_sync(0xffffffffu, mx1, 2));
            float mn0 = fmaxf(m0, mx0), mn1 = fmaxf(m1, mx1);
            float a0 = exp2f(m0 - mn0), a1 = exp2f(m1 - mn1);
            float s0 = 0.f, s1 = 0.f;
            #pragma unroll
            for (int j = 0; j < 8; j++) {
                S[j][0] = exp2f(S[j][0] - mn0); s0 += S[j][0];
                S[j][1] = exp2f(S[j][1] - mn0); s0 += S[j][1];
                S[j][2] = exp2f(S[j][2] - mn1); s1 += S[j][2];
                S[j][3] = exp2f(S[j][3] - mn1); s1 += S[j][3];
            }
            s0 += __shfl_xor_sync(0xffffffffu, s0, 1);
            s0 += __shfl_xor_sync(0xffffffffu, s0, 2);
            s1 += __shfl_xor_sync(0xffffffffu, s1, 1);
            s1 += __shfl_xor_sync(0xffffffffu, s1, 2);
            l0 = l0 * a0 + s0; l1 = l1 * a1 + s1;
            m0 = mn0; m1 = mn1;
            #pragma unroll
            for (int j = 0; j < 8; j++) {
                O[j][0] *= a0; O[j][1] *= a0;
                O[j][2] *= a1; O[j][3] *= a1;
            }

            // ---- O += P V (P split hi/lo from S fragments) ----
            #pragma unroll
            for (int ks2 = 0; ks2 < 4; ks2++) {
                const int j0 = 2 * ks2, j1 = j0 + 1;
                uint32_t ph[4], pl[4];
                ph[0] = pack_bf16(S[j0][0], S[j0][1]);
                ph[1] = pack_bf16(S[j0][2], S[j0][3]);
                ph[2] = pack_bf16(S[j1][0], S[j1][1]);
                ph[3] = pack_bf16(S[j1][2], S[j1][3]);
                pl[0] = pack_bf16(S[j0][0] - blo(ph[0]), S[j0][1] - bhi(ph[0]));
                pl[1] = pack_bf16(S[j0][2] - blo(ph[1]), S[j0][3] - bhi(ph[1]));
                pl[2] = pack_bf16(S[j1][0] - blo(ph[2]), S[j1][1] - bhi(ph[2]));
                pl[3] = pack_bf16(S[j1][2] - blo(ph[3]), S[j1][3] - bhi(ph[3]));
                #pragma unroll
                for (int dp = 0; dp < 4; dp++) {
                    int krow = ks2 * 16 + l15;
                    uint32_t a = bufb + 16384 + krow * 128 + ((((dp * 2 + lh) ^ (krow & 7)) << 4));
                    uint32_t vh[4], vl[4];
                    ldm_x4_t(vh, a);             // VH
                    ldm_x4_t(vl, a + 8192);      // VL
                    float* d0 = O[dp * 2];
                    float* d1 = O[dp * 2 + 1];
                    mma_bf16(d0, ph, vh[0], vh[1]);
                    mma_bf16(d0, ph, vl[0], vl[1]);
                    mma_bf16(d0, pl, vh[0], vh[1]);
                    mma_bf16(d1, ph, vh[2], vh[3]);
                    mma_bf16(d1, ph, vl[2], vl[3]);
                    mma_bf16(d1, pl, vh[2], vh[3]);
                }
            }
            __syncthreads();
        }

        // ---- normalize + write out ----
        float inv0 = 1.f / l0, inv1 = 1.f / l1;
        int r0 = qbase + wid * 16 + (lane >> 2);
        #pragma unroll
        for (int j = 0; j < 8; j++) {
            int dc = j * 8 + (lane & 3) * 2;
            *(float2*)(out + hb + (size_t)r0 * 64 + dc) =
                make_float2(O[j][0] * inv0, O[j][1] * inv0);
            *(float2*)(out + hb + (size_t)(r0 + 8) * 64 + dc) =
                make_float2(O[j][2] * inv1, O[j][3] * inv1);
        }
        __syncthreads();
    }
}

extern "C" void kernel_launch(void* const* d_in, const int* in_sizes, int n_in,
                              void* d_out, int out_size)
{
    const float* x  = (const float*)d_in[0];
    const float* Wq = (const float*)d_in[1];
    const float* bq = (const float*)d_in[2];
    const float* Wk = (const float*)d_in[3];
    const float* bk = (const float*)d_in[4];
    const float* Wv = (const float*)d_in[5];
    const float* bv = (const float*)d_in[6];
    float* out = (float*)d_out;

    wprep<<<192 * DD / 256, 256>>>(Wq, Wk, Wv);

    cudaFuncSetAttribute(proj_mma, cudaFuncAttributeMaxDynamicSharedMemorySize, PROJ_SMEM);
    proj_mma<<<NROWS / 128, 256, PROJ_SMEM>>>(x, bq, bk, bv);

    cudaFuncSetAttribute(flash, cudaFuncAttributeMaxDynamicSharedMemorySize, FLASH_SMEM);
    dim3 g(16, BB);
    flash<<<g, 128, FLASH_SMEM>>>(out);
}

// round 5
// speedup vs baseline: 3.9428x; 1.0031x over previous
#include <cuda_runtime.h>
#include <cuda_bf16.h>
#include <math.h>
#include <stdint.h>

#define BB 8
#define TT 2048
#define DD 1024
#define HH 64
#define NROWS (BB*TT)

__device__ __nv_bfloat16 g_qh[NROWS*HH], g_ql[NROWS*HH];
__device__ __nv_bfloat16 g_kh[NROWS*HH], g_kl[NROWS*HH];
__device__ __nv_bfloat16 g_vh[NROWS*HH], g_vl[NROWS*HH];
__device__ __nv_bfloat16 g_wt_h[192*DD];   // W^T hi [n][k] (q part pre-scaled)
__device__ __nv_bfloat16 g_wt_l[192*DD];   // W^T lo [n][k]

#define QSCALE (0.125f * 1.44269504f)

// ---------------------------------------------------------------------------
// Helpers (base sm_100 ISA: ldmatrix / mma.sync / cp.async)
// ---------------------------------------------------------------------------
__device__ __forceinline__ uint32_t smem_u32(const void* p) {
    uint32_t a;
    asm("{ .reg .u64 t; cvta.to.shared.u64 t, %1; cvt.u32.u64 %0, t; }" : "=r"(a) : "l"(p));
    return a;
}
__device__ __forceinline__ void ldm_x4(uint32_t* r, uint32_t addr) {
    asm volatile("ldmatrix.sync.aligned.m8n8.x4.shared.b16 {%0,%1,%2,%3}, [%4];"
                 : "=r"(r[0]), "=r"(r[1]), "=r"(r[2]), "=r"(r[3]) : "r"(addr));
}
__device__ __forceinline__ void ldm_x4_t(uint32_t* r, uint32_t addr) {
    asm volatile("ldmatrix.sync.aligned.m8n8.x4.trans.shared.b16 {%0,%1,%2,%3}, [%4];"
                 : "=r"(r[0]), "=r"(r[1]), "=r"(r[2]), "=r"(r[3]) : "r"(addr));
}
__device__ __forceinline__ void mma_bf16(float* c, const uint32_t* a, uint32_t b0, uint32_t b1) {
    asm volatile("mma.sync.aligned.m16n8k16.row.col.f32.bf16.bf16.f32 "
        "{%0,%1,%2,%3}, {%4,%5,%6,%7}, {%8,%9}, {%0,%1,%2,%3};"
        : "+f"(c[0]), "+f"(c[1]), "+f"(c[2]), "+f"(c[3])
        : "r"(a[0]), "r"(a[1]), "r"(a[2]), "r"(a[3]), "r"(b0), "r"(b1));
}
__device__ __forceinline__ uint32_t pack_bf16(float lo, float hi) {
    uint32_t d;
    asm("cvt.rn.bf16x2.f32 %0, %1, %2;" : "=r"(d) : "f"(hi), "f"(lo));
    return d;
}
__device__ __forceinline__ float blo(uint32_t u) { return __uint_as_float(u << 16); }
__device__ __forceinline__ float bhi(uint32_t u) { return __uint_as_float(u & 0xFFFF0000u); }

__device__ __forceinline__ void cp16(uint32_t dst, const void* src) {
    asm volatile("cp.async.cg.shared.global [%0], [%1], 16;"
                 :: "r"(dst), "l"(__cvta_generic_to_global(src)));
}
#define CP_COMMIT() asm volatile("cp.async.commit_group;" ::: "memory")
#define CP_WAIT0()  asm volatile("cp.async.wait_group 0;" ::: "memory")
#define CP_WAIT1()  asm volatile("cp.async.wait_group 1;" ::: "memory")

// ---------------------------------------------------------------------------
// W transpose (coalesced both sides) + bf16 hi/lo split; q cols pre-scaled.
// grid (6, 32), block (32, 8)
// ---------------------------------------------------------------------------
__global__ __launch_bounds__(256) void wprep(const float* __restrict__ Wq,
                                             const float* __restrict__ Wk,
                                             const float* __restrict__ Wv)
{
    __shared__ float tile[32][33];
    const int nb = blockIdx.x * 32, kb = blockIdx.y * 32;
    const int tx = threadIdx.x, ty = threadIdx.y;
    const float* W = (nb < 64) ? Wq : (nb < 128 ? Wk : Wv);
    const int ncol = (nb & 63) + tx;
    #pragma unroll
    for (int i = 0; i < 4; i++)
        tile[ty + 8 * i][tx] = W[(size_t)(kb + ty + 8 * i) * HH + ncol];
    __syncthreads();
    const float s = (nb < 64) ? QSCALE : 1.f;
    #pragma unroll
    for (int i = 0; i < 4; i++) {
        int n = nb + ty + 8 * i, k = kb + tx;
        float v = tile[tx][ty + 8 * i] * s;
        __nv_bfloat16 h = __float2bfloat16_rn(v);
        g_wt_h[(size_t)n * DD + k] = h;
        g_wt_l[(size_t)n * DD + k] = __float2bfloat16_rn(v - __bfloat162float(h));
    }
}

// ---------------------------------------------------------------------------
// QKV projection via mma.sync bf16-split, cp.async double-buffered.
// CTA: M=128 x N=192, K=1024 in 16 chunks of 64. 8 warps (4x2), tile 32x96.
// ---------------------------------------------------------------------------
#define PJ_XR(s) ((s) * 32768)             // raw fp32 x tile, 2 stages
#define PJ_B(s)  (65536 + (s) * 49152)     // BH; BL at +24576
#define PJ_AH 163840
#define PJ_AL 180224
#define PROJ_SMEM 196608

__device__ __forceinline__ void proj_issue_stage(uint32_t sb, int st, int c,
    const float* __restrict__ x, int rowbase)
{
    const int tid = threadIdx.x;
    const int k0 = c * 64;
    // XR: 128 rows x 64 fp32 (256B rows), 2048 x 16B
    #pragma unroll
    for (int i = 0; i < 8; i++) {
        int idx = tid + i * 256;
        int row = idx >> 4, cc = idx & 15;
        cp16(sb + PJ_XR(st) + row * 256 + cc * 16,
             x + (size_t)(rowbase + row) * DD + k0 + cc * 4);
    }
    // B: 192 rows x 64 bf16 x {hi,lo}, swizzled 128B rows
    #pragma unroll
    for (int i = 0; i < 12; i++) {
        int idx = tid + i * 256;                 // < 3072
        int arr = idx >= 1536;
        int rem = idx - arr * 1536;
        int row = rem >> 3, cc = rem & 7;
        const __nv_bfloat16* src = (arr ? g_wt_l : g_wt_h) + (size_t)row * DD + k0 + cc * 8;
        cp16(sb + PJ_B(st) + arr * 24576 + row * 128 + (((cc ^ (row & 7)) << 4)), src);
    }
    CP_COMMIT();
}

__global__ __launch_bounds__(256) void proj_mma(
    const float* __restrict__ x,
    const float* __restrict__ bq, const float* __restrict__ bk, const float* __restrict__ bv)
{
    extern __shared__ __align__(1024) char smem[];
    const uint32_t sb = smem_u32(smem);
    const int tid = threadIdx.x;
    const int wid = tid >> 5, lane = tid & 31;
    const int warpM = wid >> 1, warpN = wid & 1;
    const int rowbase = blockIdx.x * 128;
    const int l15 = lane & 15, lh = lane >> 4;

    float acc[2][12][4];
    #pragma unroll
    for (int m = 0; m < 2; m++)
        #pragma unroll
        for (int n = 0; n < 12; n++)
            #pragma unroll
            for (int e = 0; e < 4; e++) acc[m][n][e] = 0.f;

    proj_issue_stage(sb, 0, 0, x, rowbase);

    for (int c = 0; c < 16; c++) {
        const int st = c & 1;
        if (c + 1 < 16) { proj_issue_stage(sb, st ^ 1, c + 1, x, rowbase); CP_WAIT1(); }
        else CP_WAIT0();
        __syncthreads();

        // Convert XR (fp32) -> AH/AL (bf16 hi/lo, swizzled)
        {
            const int r = tid >> 1, hf = tid & 1;
            const char* xr = smem + PJ_XR(st) + r * 256 + hf * 128;
            #pragma unroll
            for (int j = 0; j < 4; j++) {
                float4 v0 = *(const float4*)(xr + j * 32);
                float4 v1 = *(const float4*)(xr + j * 32 + 16);
                uint32_t h0 = pack_bf16(v0.x, v0.y), h1 = pack_bf16(v0.z, v0.w);
                uint32_t h2 = pack_bf16(v1.x, v1.y), h3 = pack_bf16(v1.z, v1.w);
                uint32_t l0 = pack_bf16(v0.x - blo(h0), v0.y - bhi(h0));
                uint32_t l1 = pack_bf16(v0.z - blo(h1), v0.w - bhi(h1));
                uint32_t l2 = pack_bf16(v1.x - blo(h2), v1.y - bhi(h2));
                uint32_t l3 = pack_bf16(v1.z - blo(h3), v1.w - bhi(h3));
                int sw = r * 128 + ((((hf * 4 + j) ^ (r & 7)) << 4));
                *(uint4*)(smem + PJ_AH + sw) = make_uint4(h0, h1, h2, h3);
                *(uint4*)(smem + PJ_AL + sw) = make_uint4(l0, l1, l2, l3);
            }
        }
        __syncthreads();

        const uint32_t bbase = sb + PJ_B(st);
        #pragma unroll
        for (int ks = 0; ks < 4; ks++) {
            uint32_t ah[2][4], al[2][4];
            #pragma unroll
            for (int m = 0; m < 2; m++) {
                int row = warpM * 32 + m * 16 + l15;
                uint32_t a = sb + row * 128 + ((((ks * 2 + lh) ^ (row & 7)) << 4));
                ldm_x4(ah[m], a + PJ_AH);
                ldm_x4(al[m], a + PJ_AL);
            }
            #pragma unroll
            for (int np = 0; np < 6; np++) {
                int n = warpN * 96 + np * 16 + l15;
                uint32_t a = bbase + n * 128 + ((((ks * 2 + lh) ^ (n & 7)) << 4));
                uint32_t bh[4], bl[4];
                ldm_x4(bh, a);
                ldm_x4(bl, a + 24576);
                #pragma unroll
                for (int m = 0; m < 2; m++)
                    #pragma unroll
                    for (int sub = 0; sub < 2; sub++) {
                        float* cc = acc[m][np * 2 + sub];
                        mma_bf16(cc, ah[m], bh[sub], bh[sub + 2]);
                        mma_bf16(cc, ah[m], bl[sub], bl[sub + 2]);
                        mma_bf16(cc, al[m], bh[sub], bh[sub + 2]);
                    }
            }
        }
        __syncthreads();
    }

    // Epilogue: bias + bf16 hi/lo split store
    #pragma unroll
    for (int m = 0; m < 2; m++) {
        int r0 = rowbase + warpM * 32 + m * 16 + (lane >> 2);
        #pragma unroll
        for (int nt = 0; nt < 12; nt++) {
            int g = warpN * 96 + nt * 8 + (lane & 3) * 2;
            __nv_bfloat16 *dh, *dl; const float* bias; int cc; float s;
            if (g < 64)       { dh = g_qh; dl = g_ql; bias = bq; cc = g;       s = QSCALE; }
            else if (g < 128) { dh = g_kh; dl = g_kl; bias = bk; cc = g - 64;  s = 1.f; }
            else              { dh = g_vh; dl = g_vl; bias = bv; cc = g - 128; s = 1.f; }
            float b0 = bias[cc] * s, b1 = bias[cc + 1] * s;
            float v0 = acc[m][nt][0] + b0, v1 = acc[m][nt][1] + b1;
            float v2 = acc[m][nt][2] + b0, v3 = acc[m][nt][3] + b1;
            uint32_t h0 = pack_bf16(v0, v1);
            uint32_t l0 = pack_bf16(v0 - blo(h0), v1 - bhi(h0));
            uint32_t h1 = pack_bf16(v2, v3);
            uint32_t l1 = pack_bf16(v2 - blo(h1), v3 - bhi(h1));
            *(uint32_t*)((char*)dh + ((size_t)r0 * 64 + cc) * 2) = h0;
            *(uint32_t*)((char*)dl + ((size_t)r0 * 64 + cc) * 2) = l0;
            *(uint32_t*)((char*)dh + ((size_t)(r0 + 8) * 64 + cc) * 2) = h1;
            *(uint32_t*)((char*)dl + ((size_t)(r0 + 8) * 64 + cc) * 2) = l1;
        }
    }
}

// ---------------------------------------------------------------------------
// Flash attention (causal), KT=128 per iteration (2x ILP, half softmax rate).
// 4 warps x 16 q-rows (QT=64). Pairing (p, 31-p): every CTA = 17 iterations.
// Double-buffered cp.async K/V stages.
// ---------------------------------------------------------------------------
#define FL_QH 0
#define FL_QL 8192
#define FL_BUF 16384
#define FL_STAGE 65536                 // KH(16K) KL(16K) VH(16K) VL(16K)
#define FLASH_SMEM (16384 + 2*65536)   // 147456

__device__ __forceinline__ void flash_issue_stage(uint32_t sb, int st, int kbase, size_t hb)
{
    const int tid = threadIdx.x;
    const uint32_t stb = sb + FL_BUF + st * FL_STAGE;
    #pragma unroll
    for (int i = 0; i < 32; i++) {
        int idx = tid + i * 128;                // < 4096
        int arr = idx >> 10;
        int rem = idx & 1023;
        int row = rem >> 3, cc = rem & 7;
        const __nv_bfloat16* base = arr == 0 ? g_kh : arr == 1 ? g_kl : arr == 2 ? g_vh : g_vl;
        cp16(stb + arr * 16384 + row * 128 + (((cc ^ (row & 7)) << 4)),
             base + hb + (size_t)(kbase + row) * 64 + cc * 8);
    }
    CP_COMMIT();
}

__global__ __launch_bounds__(128) void flash(float* __restrict__ out)
{
    extern __shared__ __align__(1024) char smem[];
    const uint32_t sb = smem_u32(smem);
    const int tid = threadIdx.x;
    const int wid = tid >> 5, lane = tid & 31;
    const int l15 = lane & 15, lh = lane >> 4;
    const int pr = blockIdx.x;
    const int b  = blockIdx.y;
    const size_t hb = (size_t)b * TT * HH;

    #pragma unroll 1
    for (int half = 0; half < 2; half++) {
        const int qtile = half ? (31 - pr) : pr;
        const int qbase = qtile * 64;
        const int nkt = qtile / 2 + 1;

        // Q load (hi/lo) + stage 0 in one commit group
        #pragma unroll
        for (int i = 0; i < 8; i++) {
            int idx = tid + i * 128;                 // < 1024
            int arr = idx >> 9, rem = idx & 511;
            int row = rem >> 3, cc = rem & 7;
            const __nv_bfloat16* src = (arr == 0 ? g_qh : g_ql) + hb + (size_t)(qbase + row) * 64 + cc * 8;
            cp16(sb + (arr ? FL_QL : FL_QH) + row * 128 + (((cc ^ (row & 7)) << 4)), src);
        }
        flash_issue_stage(sb, 0, 0, hb);

        float O[8][4];
        float m0 = -1e30f, m1 = -1e30f, l0 = 0.f, l1 = 0.f;
        #pragma unroll
        for (int j = 0; j < 8; j++)
            #pragma unroll
            for (int e = 0; e < 4; e++) O[j][e] = 0.f;

        for (int kt = 0; kt < nkt; kt++) {
            const uint32_t bufb = sb + FL_BUF + (kt & 1) * FL_STAGE;
            if (kt + 1 < nkt) { flash_issue_stage(sb, (kt + 1) & 1, (kt + 1) * 128, hb); CP_WAIT1(); }
            else CP_WAIT0();
            __syncthreads();

            // ---- S = Q K^T, 16 x 128 per warp ----
            float S[16][4];
            #pragma unroll
            for (int j = 0; j < 16; j++)
                #pragma unroll
                for (int e = 0; e < 4; e++) S[j][e] = 0.f;

            #pragma unroll
            for (int ks = 0; ks < 4; ks++) {
                uint32_t Qh[4], Ql[4];
                {
                    int row = wid * 16 + l15;
                    uint32_t a = sb + row * 128 + ((((ks * 2 + lh) ^ (row & 7)) << 4));
                    ldm_x4(Qh, a + FL_QH);
                    ldm_x4(Ql, a + FL_QL);
                }
                #pragma unroll
                for (int np = 0; np < 8; np++) {
                    int n = np * 16 + l15;
                    uint32_t a = bufb + n * 128 + ((((ks * 2 + lh) ^ (n & 7)) << 4));
                    uint32_t kh[4], kl[4];
                    ldm_x4(kh, a);             // KH
                    ldm_x4(kl, a + 16384);     // KL
                    #pragma unroll
                    for (int sub = 0; sub < 2; sub++) {
                        float* cc = S[np * 2 + sub];
                        mma_bf16(cc, Qh, kh[sub], kh[sub + 2]);
                        mma_bf16(cc, Qh, kl[sub], kl[sub + 2]);
                        mma_bf16(cc, Ql, kh[sub], kh[sub + 2]);
                    }
                }
            }

            // ---- causal mask (last tile only) ----
            const int rl0 = qbase + wid * 16 + (lane >> 2), rl1 = rl0 + 8;
            if (kt == nkt - 1) {
                const int cb = kt * 128 + (lane & 3) * 2;
                #pragma unroll
                for (int j = 0; j < 16; j++) {
                    int kc = cb + j * 8;
                    if (kc     > rl0) S[j][0] = -1e30f;
                    if (kc + 1 > rl0) S[j][1] = -1e30f;
                    if (kc     > rl1) S[j][2] = -1e30f;
                    if (kc + 1 > rl1) S[j][3] = -1e30f;
                }
            }

            // ---- online softmax (log2 units) ----
            float mx0 = -1e30f, mx1 = -1e30f;
            #pragma unroll
            for (int j = 0; j < 16; j++) {
                mx0 = fmaxf(mx0, fmaxf(S[j][0], S[j][1]));
                mx1 = fmaxf(mx1, fmaxf(S[j][2], S[j][3]));
            }
            mx0 = fmaxf(mx0, __shfl_xor_sync(0xffffffffu, mx0, 1));
            mx0 = fmaxf(mx0, __shfl_xor_sync(0xffffffffu, mx0, 2));
            mx1 = fmaxf(mx1, __shfl_xor_sync(0xffffffffu, mx1, 1));
            mx1 = fmaxf(mx1, __shfl_xor_sync(0xffffffffu, mx1, 2));
            float mn0 = fmaxf(m0, mx0), mn1 = fmaxf(m1, mx1);
            float a0 = exp2f(m0 - mn0), a1 = exp2f(m1 - mn1);
            float s0 = 0.f, s1 = 0.f;
            #pragma unroll
            for (int j = 0; j < 16; j++) {
                S[j][0] = exp2f(S[j][0] - mn0); s0 += S[j][0];
                S[j][1] = exp2f(S[j][1] - mn0); s0 += S[j][1];
                S[j][2] = exp2f(S[j][2] - mn1); s1 += S[j][2];
                S[j][3] = exp2f(S[j][3] - mn1); s1 += S[j][3];
            }
            s0 += __shfl_xor_sync(0xffffffffu, s0, 1);
            s0 += __shfl_xor_sync(0xffffffffu, s0, 2);
            s1 += __shfl_xor_sync(0xffffffffu, s1, 1);
            s1 += __shfl_xor_sync(0xffffffffu, s1, 2);
            l0 = l0 * a0 + s0; l1 = l1 * a1 + s1;
            m0 = mn0; m1 = mn1;
            #pragma unroll
            for (int j = 0; j < 8; j++) {
                O[j][0] *= a0; O[j][1] *= a0;
                O[j][2] *= a1; O[j][3] *= a1;
            }

            // ---- O += P V (K-dim = 128) ----
            #pragma unroll
            for (int ks2 = 0; ks2 < 8; ks2++) {
                const int j0 = 2 * ks2, j1 = j0 + 1;
                uint32_t ph[4], pl[4];
                ph[0] = pack_bf16(S[j0][0], S[j0][1]);
                ph[1] = pack_bf16(S[j0][2], S[j0][3]);
                ph[2] = pack_bf16(S[j1][0], S[j1][1]);
                ph[3] = pack_bf16(S[j1][2], S[j1][3]);
                pl[0] = pack_bf16(S[j0][0] - blo(ph[0]), S[j0][1] - bhi(ph[0]));
                pl[1] = pack_bf16(S[j0][2] - blo(ph[1]), S[j0][3] - bhi(ph[1]));
                pl[2] = pack_bf16(S[j1][0] - blo(ph[2]), S[j1][1] - bhi(ph[2]));
                pl[3] = pack_bf16(S[j1][2] - blo(ph[3]), S[j1][3] - bhi(ph[3]));
                #pragma unroll
                for (int dp = 0; dp < 4; dp++) {
                    int krow = ks2 * 16 + l15;
                    uint32_t a = bufb + 32768 + krow * 128 + ((((dp * 2 + lh) ^ (krow & 7)) << 4));
                    uint32_t vh[4], vl[4];
                    ldm_x4_t(vh, a);             // VH
                    ldm_x4_t(vl, a + 16384);     // VL
                    float* d0 = O[dp * 2];
                    float* d1 = O[dp * 2 + 1];
                    mma_bf16(d0, ph, vh[0], vh[1]);
                    mma_bf16(d0, ph, vl[0], vl[1]);
                    mma_bf16(d0, pl, vh[0], vh[1]);
                    mma_bf16(d1, ph, vh[2], vh[3]);
                    mma_bf16(d1, ph, vl[2], vl[3]);
                    mma_bf16(d1, pl, vh[2], vh[3]);
                }
            }
            __syncthreads();
        }

        // ---- normalize + write out ----
        float inv0 = 1.f / l0, inv1 = 1.f / l1;
        int r0 = qbase + wid * 16 + (lane >> 2);
        #pragma unroll
        for (int j = 0; j < 8; j++) {
            int dc = j * 8 + (lane & 3) * 2;
            *(float2*)(out + hb + (size_t)r0 * 64 + dc) =
                make_float2(O[j][0] * inv0, O[j][1] * inv0);
            *(float2*)(out + hb + (size_t)(r0 + 8) * 64 + dc) =
                make_float2(O[j][2] * inv1, O[j][3] * inv1);
        }
    }
}

extern "C" void kernel_launch(void* const* d_in, const int* in_sizes, int n_in,
                              void* d_out, int out_size)
{
    const float* x  = (const float*)d_in[0];
    const float* Wq = (const float*)d_in[1];
    const float* bq = (const float*)d_in[2];
    const float* Wk = (const float*)d_in[3];
    const float* bk = (const float*)d_in[4];
    const float* Wv = (const float*)d_in[5];
    const float* bv = (const float*)d_in[6];
    float* out = (float*)d_out;

    dim3 wg(6, 32), wb(32, 8);
    wprep<<<wg, wb>>>(Wq, Wk, Wv);

    cudaFuncSetAttribute(proj_mma, cudaFuncAttributeMaxDynamicSharedMemorySize, PROJ_SMEM);
    proj_mma<<<NROWS / 128, 256, PROJ_SMEM>>>(x, bq, bk, bv);

    cudaFuncSetAttribute(flash, cudaFuncAttributeMaxDynamicSharedMemorySize, FLASH_SMEM);
    dim3 g(16, BB);
    flash<<<g, 128, FLASH_SMEM>>>(out);
}